// round 7
// baseline (speedup 1.0000x reference)
#include <cuda_runtime.h>
#include <cuda_bf16.h>
#include <cstdint>

#define NN 100000
#define NE 1600000
#define NB_SCAN 391   // ceil(NN/256)

// ---------------- scratch (static device globals; no allocation) ----------------
__device__ int   g_is64;
__device__ int   g_cnt[NN];
__device__ int   g_cursor[NN];
__device__ int   g_rowptr[NN + 1];
__device__ float g_dinv[NN];
__device__ int   g_csr_src[NE];
__device__ float g_Y[(size_t)NN * 192];   // stored as [n][p][f], p=12, f=16
__device__ int   g_bsum[512];
__device__ int   g_boff[512];
__device__ float g_Mz[16 * 64];
__device__ float g_Mh[16 * 64];
__device__ float g_cz[64];
__device__ float g_ch[64];
__device__ float g_probs[12];

// edge_index may be int32 or int64 depending on JAX x64 config; detect at runtime.
__device__ __forceinline__ int load_edge(const void* ei, long long pos, int is64) {
    if (is64) return (int)((const long long*)ei)[pos];
    return ((const int*)ei)[pos];
}

// ---------------- K_detect: int64 vs int32 edge dtype ----------------
__global__ void k_detect(const unsigned int* __restrict__ ew) {
    __shared__ unsigned int sh[256];
    int t = threadIdx.x;
    unsigned int v = 0;
    // odd 32-bit words 1,3,...,8191: high words (all 0) if int64, random ids if int32
    for (int i = t; i < 4096; i += 256) v |= ew[2 * i + 1];
    sh[t] = v;
    __syncthreads();
    for (int off = 128; off > 0; off >>= 1) {
        if (t < off) sh[t] |= sh[t + off];
        __syncthreads();
    }
    if (t == 0) g_is64 = (sh[0] == 0u) ? 1 : 0;
}

// ---------------- K0: fold weights + softmax(attn) ----------------
__global__ void k_prep(const float* __restrict__ attn,
                       const float* __restrict__ czw, const float* __restrict__ czb,
                       const float* __restrict__ chw, const float* __restrict__ chb,
                       const float* __restrict__ lzw, const float* __restrict__ lzb,
                       const float* __restrict__ lhw, const float* __restrict__ lhb) {
    int t = threadIdx.x;
    for (int idx = t; idx < 1024; idx += 128) {
        int f = idx >> 6, j = idx & 63;
        float sz = 0.f, sh = 0.f;
        for (int k = 0; k < 64; k++) {
            sz = fmaf(czw[f * 64 + k], lzw[k * 64 + j], sz);
            sh = fmaf(chw[f * 64 + k], lhw[k * 64 + j], sh);
        }
        g_Mz[idx] = sz;
        g_Mh[idx] = sh;
    }
    for (int j = t; j < 64; j += 128) {
        float sz = lzb[j], sh = lhb[j];
        for (int k = 0; k < 64; k++) {
            sz = fmaf(czb[k], lzw[k * 64 + j], sz);
            sh = fmaf(chb[k], lhw[k * 64 + j], sh);
        }
        g_cz[j] = sz;
        g_ch[j] = sh;
    }
    if (t == 0) {
        float m = attn[0];
        for (int p = 1; p < 12; p++) m = fmaxf(m, attn[p]);
        float e[12], s = 0.f;
        for (int p = 0; p < 12; p++) { e[p] = __expf(attn[p] - m); s += e[p]; }
        float inv = 1.f / s;
        for (int p = 0; p < 12; p++) g_probs[p] = e[p] * inv;
    }
}

// ---------------- CSR build ----------------
__global__ void k_clear() {
    int i = blockIdx.x * 256 + threadIdx.x;
    if (i < NN) g_cnt[i] = 0;
}

__global__ void k_hist(const void* __restrict__ ei) {
    int e = blockIdx.x * 256 + threadIdx.x;
    int is64 = g_is64;
    if (e < NE) {
        int d = load_edge(ei, (long long)NE + e, is64);
        atomicAdd(&g_cnt[d], 1);
    }
}

__global__ void k_scan1() {
    __shared__ int sh[256];
    int t = threadIdx.x;
    int i = blockIdx.x * 256 + t;
    int v = (i < NN) ? g_cnt[i] : 0;
    sh[t] = v;
    __syncthreads();
    for (int off = 1; off < 256; off <<= 1) {
        int add = (t >= off) ? sh[t - off] : 0;
        __syncthreads();
        sh[t] += add;
        __syncthreads();
    }
    int incl = sh[t];
    if (i < NN) g_rowptr[i] = incl - v;       // block-local exclusive
    if (t == 255) g_bsum[blockIdx.x] = incl;  // block total
}

__global__ void k_scan2() {
    __shared__ int sh[512];
    int t = threadIdx.x;
    int v = (t < NB_SCAN) ? g_bsum[t] : 0;
    sh[t] = v;
    __syncthreads();
    for (int off = 1; off < 512; off <<= 1) {
        int add = (t >= off) ? sh[t - off] : 0;
        __syncthreads();
        sh[t] += add;
        __syncthreads();
    }
    g_boff[t] = sh[t] - v;  // exclusive
}

__global__ void k_scan3() {
    int i = blockIdx.x * 256 + threadIdx.x;
    if (i < NN) {
        int r = g_rowptr[i] + g_boff[i >> 8];
        g_rowptr[i] = r;
        g_cursor[i] = r;
        g_dinv[i] = rsqrtf((float)(g_cnt[i] + 1));  // +1 self-loop
    }
    if (i == 0) g_rowptr[NN] = NE;
}

__global__ void k_fill(const void* __restrict__ ei) {
    int e = blockIdx.x * 256 + threadIdx.x;
    int is64 = g_is64;
    if (e < NE) {
        int s = load_edge(ei, e, is64);
        int d = load_edge(ei, (long long)NE + e, is64);
        int pos = atomicAdd(&g_cursor[d], 1);
        g_csr_src[pos] = s;
    }
}

// ---------------- K_spmm: Y[dst] = sum_{src in N(dst)} dinv[s]*dinv[d]*X[src] + dinv[d]^2*X[dst]
// one warp per destination node; writes transposed to [n][p][f] layout ----------------
__global__ void __launch_bounds__(256) k_spmm(const float* __restrict__ x) {
    int w = blockIdx.x * 8 + (threadIdx.x >> 5);
    int lane = threadIdx.x & 31;
    if (w >= NN) return;

    float dn = g_dinv[w];
    int b = g_rowptr[w];
    int e = g_rowptr[w + 1];

    const float* xr = x + (size_t)w * 192;
    float w0 = dn * dn;
    float acc[6];
#pragma unroll
    for (int i = 0; i < 6; i++) acc[i] = w0 * __ldg(xr + lane + 32 * i);

    for (int t = b; t < e; ++t) {
        int s = g_csr_src[t];
        float wt = g_dinv[s] * dn;
        const float* xs = x + (size_t)s * 192;
#pragma unroll
        for (int i = 0; i < 6; i++)
            acc[i] = fmaf(wt, __ldg(xs + lane + 32 * i), acc[i]);
    }

    float* yr = g_Y + (size_t)w * 192;
#pragma unroll
    for (int i = 0; i < 6; i++) {
        int k = lane + 32 * i;     // k = f*12 + p in source layout
        int f = k / 12;
        int p = k - f * 12;
        yr[p * 16 + f] = acc[i];   // transposed: [p][f]
    }
}

// ---------------- K_dense: per (node, 16-col chunk) GRU math + output head ----------------
__device__ __forceinline__ float tanh_fast(float v) {
    float r;
    asm("tanh.approx.f32 %0, %1;" : "=f"(r) : "f"(v));
    return r;
}

__global__ void __launch_bounds__(128) k_dense(const float* __restrict__ outw,
                                               const float* __restrict__ outb,
                                               float* __restrict__ out) {
    // padded weight layout: [f][chunk][j], chunk stride 20 floats -> chunks land on
    // disjoint bank groups {0-3},{20-23},{8-11},{28-31}: conflict-free LDS.128
    __shared__ __align__(16) float sMz[16 * 80];
    __shared__ __align__(16) float sMh[16 * 80];
    __shared__ float scz[64], sch[64], sOw[256], sOb[4], sp[12];

    int t = threadIdx.x;
    for (int idx = t; idx < 1024; idx += 128) {
        int f = idx >> 6, j = idx & 63;
        int pos = f * 80 + (j >> 4) * 20 + (j & 15);
        sMz[pos] = g_Mz[idx];
        sMh[pos] = g_Mh[idx];
    }
    for (int idx = t; idx < 64; idx += 128) { scz[idx] = g_cz[idx]; sch[idx] = g_ch[idx]; }
    for (int idx = t; idx < 256; idx += 128) sOw[idx] = outw[idx];
    if (t < 4) sOb[t] = outb[t];
    if (t < 12) sp[t] = g_probs[t];
    __syncthreads();

    int gid = blockIdx.x * 128 + t;
    int n = gid >> 2;
    int ch = gid & 3;                               // which 16-column chunk of 64
    const float4* yr = reinterpret_cast<const float4*>(g_Y + (size_t)n * 192);
    const float4* sMz4 = reinterpret_cast<const float4*>(sMz);
    const float4* sMh4 = reinterpret_cast<const float4*>(sMh);
    int wbase = ch * 5;                             // ch*20 floats = ch*5 float4

    float hac[16];
#pragma unroll
    for (int j = 0; j < 16; j++) hac[j] = 0.f;

    for (int p = 0; p < 12; p++) {
        float4 y0 = yr[p * 4 + 0], y1 = yr[p * 4 + 1];
        float4 y2 = yr[p * 4 + 2], y3 = yr[p * 4 + 3];
        float yv[16] = { y0.x, y0.y, y0.z, y0.w, y1.x, y1.y, y1.z, y1.w,
                         y2.x, y2.y, y2.z, y2.w, y3.x, y3.y, y3.z, y3.w };
        float za[16], ha[16];
#pragma unroll
        for (int j = 0; j < 16; j++) {
            za[j] = scz[ch * 16 + j];
            ha[j] = sch[ch * 16 + j];
        }
#pragma unroll
        for (int f = 0; f < 16; f++) {
            float y = yv[f];
            float4 az[4], ah[4];
#pragma unroll
            for (int q = 0; q < 4; q++) {
                az[q] = sMz4[wbase + f * 20 + q];
                ah[q] = sMh4[wbase + f * 20 + q];
            }
#pragma unroll
            for (int q = 0; q < 4; q++) {
                za[4 * q + 0] = fmaf(y, az[q].x, za[4 * q + 0]);
                za[4 * q + 1] = fmaf(y, az[q].y, za[4 * q + 1]);
                za[4 * q + 2] = fmaf(y, az[q].z, za[4 * q + 2]);
                za[4 * q + 3] = fmaf(y, az[q].w, za[4 * q + 3]);
                ha[4 * q + 0] = fmaf(y, ah[q].x, ha[4 * q + 0]);
                ha[4 * q + 1] = fmaf(y, ah[q].y, ha[4 * q + 1]);
                ha[4 * q + 2] = fmaf(y, ah[q].z, ha[4 * q + 2]);
                ha[4 * q + 3] = fmaf(y, ah[q].w, ha[4 * q + 3]);
            }
        }
        float pr = sp[p];
#pragma unroll
        for (int j = 0; j < 16; j++) {
            // pr * (1 - sigmoid(za)) = pr * 1/(1+exp(za))
            float u = pr * __fdividef(1.f, 1.f + __expf(za[j]));
            hac[j] = fmaf(u, tanh_fast(ha[j]), hac[j]);
        }
    }

    // output head: relu -> 64x4 -> softmax(4)
    float lg0 = 0.f, lg1 = 0.f, lg2 = 0.f, lg3 = 0.f;
#pragma unroll
    for (int j = 0; j < 16; j++) {
        float h = fmaxf(hac[j], 0.f);
        const float* wq = sOw + (ch * 16 + j) * 4;
        lg0 = fmaf(h, wq[0], lg0);
        lg1 = fmaf(h, wq[1], lg1);
        lg2 = fmaf(h, wq[2], lg2);
        lg3 = fmaf(h, wq[3], lg3);
    }
#pragma unroll
    for (int off = 2; off > 0; off >>= 1) {
        lg0 += __shfl_down_sync(0xffffffffu, lg0, off, 4);
        lg1 += __shfl_down_sync(0xffffffffu, lg1, off, 4);
        lg2 += __shfl_down_sync(0xffffffffu, lg2, off, 4);
        lg3 += __shfl_down_sync(0xffffffffu, lg3, off, 4);
    }
    if (ch == 0) {
        lg0 += sOb[0]; lg1 += sOb[1]; lg2 += sOb[2]; lg3 += sOb[3];
        float m = fmaxf(fmaxf(lg0, lg1), fmaxf(lg2, lg3));
        float e0 = __expf(lg0 - m), e1 = __expf(lg1 - m);
        float e2 = __expf(lg2 - m), e3 = __expf(lg3 - m);
        float inv = __fdividef(1.f, e0 + e1 + e2 + e3);
        reinterpret_cast<float4*>(out)[n] = make_float4(e0 * inv, e1 * inv, e2 * inv, e3 * inv);
    }
}

// ---------------- launch ----------------
extern "C" void kernel_launch(void* const* d_in, const int* in_sizes, int n_in,
                              void* d_out, int out_size) {
    const float* x    = (const float*)d_in[0];
    const void*  ei   = d_in[1];                    // int32 or int64, detected on device
    const float* attn = (const float*)d_in[2];
    const float* czw  = (const float*)d_in[3];
    const float* czb  = (const float*)d_in[4];
    // d_in[5], d_in[6] (conv_r_*) and d_in[11], d_in[12] (lin_r_*) are dead code: H0 == 0
    const float* chw  = (const float*)d_in[7];
    const float* chb  = (const float*)d_in[8];
    const float* lzw  = (const float*)d_in[9];
    const float* lzb  = (const float*)d_in[10];
    const float* lhw  = (const float*)d_in[13];
    const float* lhb  = (const float*)d_in[14];
    const float* ow   = (const float*)d_in[15];
    const float* ob   = (const float*)d_in[16];
    float* out = (float*)d_out;

    k_detect<<<1, 256>>>((const unsigned int*)ei);
    k_prep <<<1, 128>>>(attn, czw, czb, chw, chb, lzw, lzb, lhw, lhb);
    k_clear<<<NB_SCAN, 256>>>();
    k_hist <<<(NE + 255) / 256, 256>>>(ei);
    k_scan1<<<NB_SCAN, 256>>>();
    k_scan2<<<1, 512>>>();
    k_scan3<<<NB_SCAN, 256>>>();
    k_fill <<<(NE + 255) / 256, 256>>>(ei);
    k_spmm <<<(NN + 7) / 8, 256>>>(x);
    k_dense<<<(NN * 4 + 127) / 128, 128>>>(ow, ob, out);
}

// round 8
// speedup vs baseline: 1.0081x; 1.0081x over previous
#include <cuda_runtime.h>
#include <cuda_bf16.h>
#include <cstdint>

#define NN 100000
#define NE 1600000
#define NB_SCAN 391   // ceil(NN/256)

// ---------------- scratch (static device globals; no allocation) ----------------
__device__ int   g_is64;
__device__ int   g_cnt[NN];
__device__ int   g_cursor[NN];
__device__ int   g_rowptr[NN + 1];
__device__ float g_dinv[NN];
__device__ int   g_csr_src[NE];
__device__ float g_csr_wt[NE];            // dinv[src] per CSR slot
__device__ float g_Y[(size_t)NN * 192];   // stored as [n][p][f], p=12, f=16
__device__ int   g_bsum[512];
__device__ int   g_boff[512];
__device__ float g_Mz[16 * 64];
__device__ float g_Mh[16 * 64];
__device__ float g_cz[64];
__device__ float g_ch[64];
__device__ float g_probs[12];

// edge_index may be int32 or int64 depending on JAX x64 config; detect at runtime.
__device__ __forceinline__ int load_edge(const void* ei, long long pos, int is64) {
    if (is64) return (int)((const long long*)ei)[pos];
    return ((const int*)ei)[pos];
}

// ---------------- packed f32x2 helpers ----------------
__device__ __forceinline__ unsigned long long pack2(float v) {
    unsigned long long r;
    asm("mov.b64 %0, {%1, %1};" : "=l"(r) : "f"(v));
    return r;
}
__device__ __forceinline__ float2 unpack2(unsigned long long v) {
    float2 f;
    asm("mov.b64 {%0, %1}, %2;" : "=f"(f.x), "=f"(f.y) : "l"(v));
    return f;
}
#define FMA2(acc, a, b) asm("fma.rn.f32x2 %0, %1, %2, %0;" : "+l"(acc) : "l"(a), "l"(b))

__device__ __forceinline__ float tanh_fast(float v) {
    float r;
    asm("tanh.approx.f32 %0, %1;" : "=f"(r) : "f"(v));
    return r;
}

// ---------------- K_detect: int64 vs int32 edge dtype ----------------
__global__ void k_detect(const unsigned int* __restrict__ ew) {
    __shared__ unsigned int sh[256];
    int t = threadIdx.x;
    unsigned int v = 0;
    // odd 32-bit words 1,3,...,8191: high words (all 0) if int64, random ids if int32
    for (int i = t; i < 4096; i += 256) v |= ew[2 * i + 1];
    sh[t] = v;
    __syncthreads();
    for (int off = 128; off > 0; off >>= 1) {
        if (t < off) sh[t] |= sh[t + off];
        __syncthreads();
    }
    if (t == 0) g_is64 = (sh[0] == 0u) ? 1 : 0;
}

// ---------------- K0: fold weights + softmax(attn) ----------------
__global__ void k_prep(const float* __restrict__ attn,
                       const float* __restrict__ czw, const float* __restrict__ czb,
                       const float* __restrict__ chw, const float* __restrict__ chb,
                       const float* __restrict__ lzw, const float* __restrict__ lzb,
                       const float* __restrict__ lhw, const float* __restrict__ lhb) {
    int t = threadIdx.x;
    for (int idx = t; idx < 1024; idx += 128) {
        int f = idx >> 6, j = idx & 63;
        float sz = 0.f, sh = 0.f;
        for (int k = 0; k < 64; k++) {
            sz = fmaf(czw[f * 64 + k], lzw[k * 64 + j], sz);
            sh = fmaf(chw[f * 64 + k], lhw[k * 64 + j], sh);
        }
        g_Mz[idx] = sz;
        g_Mh[idx] = sh;
    }
    for (int j = t; j < 64; j += 128) {
        float sz = lzb[j], sh = lhb[j];
        for (int k = 0; k < 64; k++) {
            sz = fmaf(czb[k], lzw[k * 64 + j], sz);
            sh = fmaf(chb[k], lhw[k * 64 + j], sh);
        }
        g_cz[j] = sz;
        g_ch[j] = sh;
    }
    if (t == 0) {
        float m = attn[0];
        for (int p = 1; p < 12; p++) m = fmaxf(m, attn[p]);
        float e[12], s = 0.f;
        for (int p = 0; p < 12; p++) { e[p] = __expf(attn[p] - m); s += e[p]; }
        float inv = 1.f / s;
        for (int p = 0; p < 12; p++) g_probs[p] = e[p] * inv;
    }
}

// ---------------- CSR build ----------------
__global__ void k_clear() {
    int i = blockIdx.x * 256 + threadIdx.x;
    if (i < NN) g_cnt[i] = 0;
}

__global__ void k_hist(const void* __restrict__ ei) {
    int e = blockIdx.x * 256 + threadIdx.x;
    int is64 = g_is64;
    if (e < NE) {
        int d = load_edge(ei, (long long)NE + e, is64);
        atomicAdd(&g_cnt[d], 1);
    }
}

__global__ void k_scan1() {
    __shared__ int sh[256];
    int t = threadIdx.x;
    int i = blockIdx.x * 256 + t;
    int v = (i < NN) ? g_cnt[i] : 0;
    sh[t] = v;
    __syncthreads();
    for (int off = 1; off < 256; off <<= 1) {
        int add = (t >= off) ? sh[t - off] : 0;
        __syncthreads();
        sh[t] += add;
        __syncthreads();
    }
    int incl = sh[t];
    if (i < NN) g_rowptr[i] = incl - v;       // block-local exclusive
    if (t == 255) g_bsum[blockIdx.x] = incl;  // block total
}

__global__ void k_scan2() {
    __shared__ int sh[512];
    int t = threadIdx.x;
    int v = (t < NB_SCAN) ? g_bsum[t] : 0;
    sh[t] = v;
    __syncthreads();
    for (int off = 1; off < 512; off <<= 1) {
        int add = (t >= off) ? sh[t - off] : 0;
        __syncthreads();
        sh[t] += add;
        __syncthreads();
    }
    g_boff[t] = sh[t] - v;  // exclusive
}

__global__ void k_scan3() {
    int i = blockIdx.x * 256 + threadIdx.x;
    if (i < NN) {
        int r = g_rowptr[i] + g_boff[i >> 8];
        g_rowptr[i] = r;
        g_cursor[i] = r;
        g_dinv[i] = rsqrtf((float)(g_cnt[i] + 1));  // +1 self-loop
    }
    if (i == 0) g_rowptr[NN] = NE;
}

__global__ void k_fill(const void* __restrict__ ei) {
    int e = blockIdx.x * 256 + threadIdx.x;
    int is64 = g_is64;
    if (e < NE) {
        int s = load_edge(ei, e, is64);
        int d = load_edge(ei, (long long)NE + e, is64);
        int pos = atomicAdd(&g_cursor[d], 1);
        g_csr_src[pos] = s;
        g_csr_wt[pos]  = g_dinv[s];   // dinv[dst] factored out in k_spmm
    }
}

// ---------------- K_spmm: Y[d] = dn * ( dn*x[d] + sum_s dinv[s]*x[s] )
// one warp per destination node; writes transposed to [n][p][f] layout ----------------
__global__ void __launch_bounds__(256) k_spmm(const float* __restrict__ x) {
    int w = blockIdx.x * 8 + (threadIdx.x >> 5);
    int lane = threadIdx.x & 31;
    if (w >= NN) return;

    float dn = g_dinv[w];
    int b = g_rowptr[w];
    int e = g_rowptr[w + 1];

    const float* xr = x + (size_t)w * 192;
    float acc[6];
#pragma unroll
    for (int i = 0; i < 6; i++) acc[i] = dn * __ldg(xr + lane + 32 * i);

    int t = b;
    for (; t + 1 < e; t += 2) {
        int   s0 = g_csr_src[t],     s1 = g_csr_src[t + 1];
        float w0 = g_csr_wt[t],      w1 = g_csr_wt[t + 1];
        const float* x0 = x + (size_t)s0 * 192;
        const float* x1 = x + (size_t)s1 * 192;
#pragma unroll
        for (int i = 0; i < 6; i++)
            acc[i] = fmaf(w0, __ldg(x0 + lane + 32 * i), acc[i]);
#pragma unroll
        for (int i = 0; i < 6; i++)
            acc[i] = fmaf(w1, __ldg(x1 + lane + 32 * i), acc[i]);
    }
    if (t < e) {
        int   s0 = g_csr_src[t];
        float w0 = g_csr_wt[t];
        const float* x0 = x + (size_t)s0 * 192;
#pragma unroll
        for (int i = 0; i < 6; i++)
            acc[i] = fmaf(w0, __ldg(x0 + lane + 32 * i), acc[i]);
    }

    float* yr = g_Y + (size_t)w * 192;
#pragma unroll
    for (int i = 0; i < 6; i++) {
        int k = lane + 32 * i;     // k = f*12 + p in source layout
        int f = k / 12;
        int p = k - f * 12;
        yr[p * 16 + f] = dn * acc[i];   // transposed: [p][f]
    }
}

// ---------------- K_dense: 2 nodes per thread, f32x2 packed math ----------------
__global__ void __launch_bounds__(128) k_dense(const float* __restrict__ outw,
                                               const float* __restrict__ outb,
                                               float* __restrict__ out) {
    // padded weight layout: [f][chunk][j], chunk stride 20 floats -> 4 chunks hit
    // disjoint bank groups: conflict-free broadcast LDS.128 (as ulonglong2 = packed f32x2 pairs)
    __shared__ __align__(16) float sMz[16 * 80];
    __shared__ __align__(16) float sMh[16 * 80];
    __shared__ __align__(16) float scz[64];
    __shared__ __align__(16) float sch[64];
    __shared__ float sOw[256], sOb[4], sp[12];

    int t = threadIdx.x;
    for (int idx = t; idx < 1024; idx += 128) {
        int f = idx >> 6, j = idx & 63;
        int pos = f * 80 + (j >> 4) * 20 + (j & 15);
        sMz[pos] = g_Mz[idx];
        sMh[pos] = g_Mh[idx];
    }
    for (int idx = t; idx < 64; idx += 128) { scz[idx] = g_cz[idx]; sch[idx] = g_ch[idx]; }
    for (int idx = t; idx < 256; idx += 128) sOw[idx] = outw[idx];
    if (t < 4) sOb[t] = outb[t];
    if (t < 12) sp[t] = g_probs[t];
    __syncthreads();

    int gid  = blockIdx.x * 128 + t;
    int pair = gid >> 2;             // node pair index
    int ch   = gid & 3;              // which 16-col chunk of 64
    if (pair >= NN / 2) return;

    int n0 = pair * 2;
    const float4* yrA = reinterpret_cast<const float4*>(g_Y + (size_t)n0 * 192);
    const float4* yrB = yrA + 48;    // node n0+1

    const ulonglong2* mz = reinterpret_cast<const ulonglong2*>(sMz);
    const ulonglong2* mh = reinterpret_cast<const ulonglong2*>(sMh);
    const unsigned long long* cz2 = reinterpret_cast<const unsigned long long*>(scz);
    const unsigned long long* ch2 = reinterpret_cast<const unsigned long long*>(sch);
    int wbase = ch * 5;              // in 16B units (float4 == ulonglong2)

    float hacA[16], hacB[16];
#pragma unroll
    for (int j = 0; j < 16; j++) { hacA[j] = 0.f; hacB[j] = 0.f; }

    for (int p = 0; p < 12; p++) {
        float4 a0 = yrA[p * 4 + 0], a1 = yrA[p * 4 + 1];
        float4 a2 = yrA[p * 4 + 2], a3 = yrA[p * 4 + 3];
        float4 b0 = yrB[p * 4 + 0], b1 = yrB[p * 4 + 1];
        float4 b2 = yrB[p * 4 + 2], b3 = yrB[p * 4 + 3];
        float yA[16] = { a0.x, a0.y, a0.z, a0.w, a1.x, a1.y, a1.z, a1.w,
                         a2.x, a2.y, a2.z, a2.w, a3.x, a3.y, a3.z, a3.w };
        float yB[16] = { b0.x, b0.y, b0.z, b0.w, b1.x, b1.y, b1.z, b1.w,
                         b2.x, b2.y, b2.z, b2.w, b3.x, b3.y, b3.z, b3.w };

        unsigned long long zA[8], hA[8], zB[8], hB[8];
#pragma unroll
        for (int k = 0; k < 8; k++) {
            unsigned long long cz_k = cz2[ch * 8 + k];
            unsigned long long ch_k = ch2[ch * 8 + k];
            zA[k] = cz_k; zB[k] = cz_k;
            hA[k] = ch_k; hB[k] = ch_k;
        }

#pragma unroll
        for (int f = 0; f < 16; f++) {
            int base = wbase + f * 20;
            ulonglong2 wz0 = mz[base + 0], wz1 = mz[base + 1];
            ulonglong2 wz2 = mz[base + 2], wz3 = mz[base + 3];
            ulonglong2 wh0 = mh[base + 0], wh1 = mh[base + 1];
            ulonglong2 wh2 = mh[base + 2], wh3 = mh[base + 3];
            unsigned long long ya = pack2(yA[f]);
            unsigned long long yb = pack2(yB[f]);
            FMA2(zA[0], ya, wz0.x); FMA2(zA[1], ya, wz0.y);
            FMA2(zA[2], ya, wz1.x); FMA2(zA[3], ya, wz1.y);
            FMA2(zA[4], ya, wz2.x); FMA2(zA[5], ya, wz2.y);
            FMA2(zA[6], ya, wz3.x); FMA2(zA[7], ya, wz3.y);
            FMA2(hA[0], ya, wh0.x); FMA2(hA[1], ya, wh0.y);
            FMA2(hA[2], ya, wh1.x); FMA2(hA[3], ya, wh1.y);
            FMA2(hA[4], ya, wh2.x); FMA2(hA[5], ya, wh2.y);
            FMA2(hA[6], ya, wh3.x); FMA2(hA[7], ya, wh3.y);
            FMA2(zB[0], yb, wz0.x); FMA2(zB[1], yb, wz0.y);
            FMA2(zB[2], yb, wz1.x); FMA2(zB[3], yb, wz1.y);
            FMA2(zB[4], yb, wz2.x); FMA2(zB[5], yb, wz2.y);
            FMA2(zB[6], yb, wz3.x); FMA2(zB[7], yb, wz3.y);
            FMA2(hB[0], yb, wh0.x); FMA2(hB[1], yb, wh0.y);
            FMA2(hB[2], yb, wh1.x); FMA2(hB[3], yb, wh1.y);
            FMA2(hB[4], yb, wh2.x); FMA2(hB[5], yb, wh2.y);
            FMA2(hB[6], yb, wh3.x); FMA2(hB[7], yb, wh3.y);
        }

        float pr = sp[p];
#pragma unroll
        for (int k = 0; k < 8; k++) {
            float2 vz = unpack2(zA[k]);
            float2 vh = unpack2(hA[k]);
            float u0 = pr * __fdividef(1.f, 1.f + __expf(vz.x));
            float u1 = pr * __fdividef(1.f, 1.f + __expf(vz.y));
            hacA[2 * k + 0] = fmaf(u0, tanh_fast(vh.x), hacA[2 * k + 0]);
            hacA[2 * k + 1] = fmaf(u1, tanh_fast(vh.y), hacA[2 * k + 1]);
            float2 wzb = unpack2(zB[k]);
            float2 whb = unpack2(hB[k]);
            float v0 = pr * __fdividef(1.f, 1.f + __expf(wzb.x));
            float v1 = pr * __fdividef(1.f, 1.f + __expf(wzb.y));
            hacB[2 * k + 0] = fmaf(v0, tanh_fast(whb.x), hacB[2 * k + 0]);
            hacB[2 * k + 1] = fmaf(v1, tanh_fast(whb.y), hacB[2 * k + 1]);
        }
    }

    // output head: relu -> 64x4 -> softmax(4), for both nodes
#pragma unroll
    for (int nb = 0; nb < 2; nb++) {
        const float* hc = nb ? hacB : hacA;
        float lg0 = 0.f, lg1 = 0.f, lg2 = 0.f, lg3 = 0.f;
#pragma unroll
        for (int j = 0; j < 16; j++) {
            float h = fmaxf(hc[j], 0.f);
            const float* wq = sOw + (ch * 16 + j) * 4;
            lg0 = fmaf(h, wq[0], lg0);
            lg1 = fmaf(h, wq[1], lg1);
            lg2 = fmaf(h, wq[2], lg2);
            lg3 = fmaf(h, wq[3], lg3);
        }
#pragma unroll
        for (int off = 2; off > 0; off >>= 1) {
            lg0 += __shfl_down_sync(0xffffffffu, lg0, off, 4);
            lg1 += __shfl_down_sync(0xffffffffu, lg1, off, 4);
            lg2 += __shfl_down_sync(0xffffffffu, lg2, off, 4);
            lg3 += __shfl_down_sync(0xffffffffu, lg3, off, 4);
        }
        if (ch == 0) {
            lg0 += sOb[0]; lg1 += sOb[1]; lg2 += sOb[2]; lg3 += sOb[3];
            float m = fmaxf(fmaxf(lg0, lg1), fmaxf(lg2, lg3));
            float e0 = __expf(lg0 - m), e1 = __expf(lg1 - m);
            float e2 = __expf(lg2 - m), e3 = __expf(lg3 - m);
            float inv = __fdividef(1.f, e0 + e1 + e2 + e3);
            reinterpret_cast<float4*>(out)[n0 + nb] =
                make_float4(e0 * inv, e1 * inv, e2 * inv, e3 * inv);
        }
    }
}

// ---------------- launch ----------------
extern "C" void kernel_launch(void* const* d_in, const int* in_sizes, int n_in,
                              void* d_out, int out_size) {
    const float* x    = (const float*)d_in[0];
    const void*  ei   = d_in[1];                    // int32 or int64, detected on device
    const float* attn = (const float*)d_in[2];
    const float* czw  = (const float*)d_in[3];
    const float* czb  = (const float*)d_in[4];
    // d_in[5], d_in[6] (conv_r_*) and d_in[11], d_in[12] (lin_r_*) are dead code: H0 == 0
    const float* chw  = (const float*)d_in[7];
    const float* chb  = (const float*)d_in[8];
    const float* lzw  = (const float*)d_in[9];
    const float* lzb  = (const float*)d_in[10];
    const float* lhw  = (const float*)d_in[13];
    const float* lhb  = (const float*)d_in[14];
    const float* ow   = (const float*)d_in[15];
    const float* ob   = (const float*)d_in[16];
    float* out = (float*)d_out;

    k_detect<<<1, 256>>>((const unsigned int*)ei);
    k_prep <<<1, 128>>>(attn, czw, czb, chw, chb, lzw, lzb, lhw, lhb);
    k_clear<<<NB_SCAN, 256>>>();
    k_hist <<<(NE + 255) / 256, 256>>>(ei);
    k_scan1<<<NB_SCAN, 256>>>();
    k_scan2<<<1, 512>>>();
    k_scan3<<<NB_SCAN, 256>>>();
    k_fill <<<(NE + 255) / 256, 256>>>(ei);
    k_spmm <<<(NN + 7) / 8, 256>>>(x);
    k_dense<<<(NN * 2 + 127) / 128, 128>>>(ow, ob, out);
}